// round 1
// baseline (speedup 1.0000x reference)
#include <cuda_runtime.h>

#define CC    256   // channels
#define LAGS  256   // receptive field of composed filter
#define BATCH 64
#define DEC   32
#define ENC   512
#define TTOT  543   // ENC + DEC - 1
#define HID   512
#define HC    192   // W1 columns cached in smem (per decode block)
#define BPB   2     // batches per decode block

// Persistent scratch (no allocations allowed).
__device__ float g_WT_A[LAGS * CC];   // layout [tau][c]
__device__ float g_WT_B[LAGS * CC];
__device__ float g_bA[CC];
__device__ float g_bB[CC];
__device__ float g_feat_enc[BATCH * DEC * CC];  // [(b*DEC+i)*CC + c]

// ---------------------------------------------------------------------------
// 1) Init composed filter with conv0 (dilation 1, K=2):
//    y[t] = w[c,0,0]*x[t-1] + w[c,0,1]*x[t]  ->  lag0 = w[...,1], lag1 = w[...,0]
// ---------------------------------------------------------------------------
__global__ void k_init(const float* __restrict__ c0w, const float* __restrict__ c0b) {
    int tid = blockIdx.x * 256 + threadIdx.x;   // grid 256x256 covers 65536
    int tau = tid >> 8, c = tid & 255;
    float v = 0.f;
    if (tau == 0)      v = c0w[c * 2 + 1];
    else if (tau == 1) v = c0w[c * 2 + 0];
    g_WT_A[tid] = v;
    if (tid < CC) g_bA[tid] = c0b[tid];
}

// ---------------------------------------------------------------------------
// 2) Compose one conv layer into the running filter:
//    Wnext[tau][co] = sum_ci Wp[tau][ci]*w[co,ci,1] + Wp[tau-d][ci]*w[co,ci,0]
//    bnext[co]      = b[co] + sum_ci (w[co,ci,0]+w[co,ci,1]) * bprev[ci]
//    Tiled 32(tau) x 32(co), k-chunk 32, 256 threads, 2x2 micro-tile.
// ---------------------------------------------------------------------------
__global__ void k_compose(int flip, const float* __restrict__ w,
                          const float* __restrict__ b, int d) {
    const float* src  = flip ? g_WT_B : g_WT_A;
    float*       dst  = flip ? g_WT_A : g_WT_B;
    const float* srcb = flip ? g_bB   : g_bA;
    float*       dstb = flip ? g_bA   : g_bB;

    __shared__ float As[32][33], Ass[32][33], B1[32][33], B0[32][33];
    int t   = threadIdx.x;
    int co0 = blockIdx.x * 32;
    int tau0 = blockIdx.y * 32;
    int tx = t & 15, ty = t >> 4;   // 16x16
    float acc00 = 0.f, acc01 = 0.f, acc10 = 0.f, acc11 = 0.f;

    for (int kc = 0; kc < CC; kc += 32) {
        #pragma unroll
        for (int e = 0; e < 4; e++) {
            int li = e * 256 + t;
            // A tiles: ci (col) fastest -> coalesced
            int r = li >> 5, cidx = li & 31;
            As[r][cidx] = src[(tau0 + r) * CC + kc + cidx];
            int ts = tau0 + r - d;
            Ass[r][cidx] = (ts >= 0) ? src[ts * CC + kc + cidx] : 0.f;
            // B tiles: ci (row) fastest -> coalesced float2 over (k0,k1)
            int rb = li & 31, cb2 = li >> 5;
            float2 wv = *(const float2*)(w + ((size_t)(co0 + cb2) * CC + kc + rb) * 2);
            B0[rb][cb2] = wv.x;
            B1[rb][cb2] = wv.y;
        }
        __syncthreads();
        #pragma unroll
        for (int ci = 0; ci < 32; ci++) {
            float a0 = As[ty * 2][ci],  a1 = As[ty * 2 + 1][ci];
            float s0 = Ass[ty * 2][ci], s1 = Ass[ty * 2 + 1][ci];
            float b1a = B1[ci][tx * 2], b1b = B1[ci][tx * 2 + 1];
            float b0a = B0[ci][tx * 2], b0b = B0[ci][tx * 2 + 1];
            acc00 += a0 * b1a + s0 * b0a;
            acc01 += a0 * b1b + s0 * b0b;
            acc10 += a1 * b1a + s1 * b0a;
            acc11 += a1 * b1b + s1 * b0b;
        }
        __syncthreads();
    }
    dst[(tau0 + ty * 2    ) * CC + co0 + tx * 2    ] = acc00;
    dst[(tau0 + ty * 2    ) * CC + co0 + tx * 2 + 1] = acc01;
    dst[(tau0 + ty * 2 + 1) * CC + co0 + tx * 2    ] = acc10;
    dst[(tau0 + ty * 2 + 1) * CC + co0 + tx * 2 + 1] = acc11;

    if (blockIdx.y == 0 && t < 32) {
        int co = co0 + t;
        float acc = b[co];
        for (int ci = 0; ci < CC; ci++) {
            float2 wv = *(const float2*)(w + ((size_t)co * CC + ci) * 2);
            acc += (wv.x + wv.y) * srcb[ci];
        }
        dstb[co] = acc;
    }
}

// ---------------------------------------------------------------------------
// 3) Encoder precompute:
//    feat_enc[b,i,c] = beff[c] + sum_{tau=i..255} Weff[c,tau] * x[b, 511+i-tau]
//    Needed x indices fall in [256, 511] only.
//    Grid: (b=64, ctile=4). 256 threads: c_l = t&63 (64 c per tile), ig = t>>6
//    handles 8 decode steps i = ig*8..ig*8+7.
// ---------------------------------------------------------------------------
__global__ void k_featenc(const float* __restrict__ x) {
    __shared__ float xs[256];
    __shared__ float Ws[32][65];
    int b = blockIdx.x, ct = blockIdx.y;
    int t = threadIdx.x;
    xs[t] = x[b * TTOT + 256 + t];
    int c_l = t & 63, ig = t >> 6;
    float acc[8] = {0.f, 0.f, 0.f, 0.f, 0.f, 0.f, 0.f, 0.f};

    for (int tc = 0; tc < LAGS; tc += 32) {
        __syncthreads();
        #pragma unroll
        for (int e = 0; e < 8; e++) {
            int li = e * 256 + t;
            int tt = li >> 6, cc = li & 63;
            Ws[tt][cc] = g_WT_B[(tc + tt) * CC + ct * 64 + cc];
        }
        __syncthreads();
        for (int tt = 0; tt < 32; tt++) {
            int tau = tc + tt;
            float wv = Ws[tt][c_l];
            #pragma unroll
            for (int r = 0; r < 8; r++) {
                int i = ig * 8 + r;
                if (tau >= i) acc[r] += wv * xs[255 + i - tau];
            }
        }
    }
    float bv = g_bB[ct * 64 + c_l];
    #pragma unroll
    for (int r = 0; r < 8; r++) {
        int i = ig * 8 + r;
        g_feat_enc[(b * DEC + i) * CC + ct * 64 + c_l] = acc[r] + bv;
    }
}

// ---------------------------------------------------------------------------
// 4) Autoregressive decode: one block per 2 batch elements, 32 sequential
//    steps, no cross-block dependence. W1: first HC columns cached in SMEM,
//    the rest streamed from L2 each step.
// ---------------------------------------------------------------------------
__global__ void __launch_bounds__(256, 1)
k_decode(const float* __restrict__ w1, const float* __restrict__ b1,
         const float* __restrict__ w2, const float* __restrict__ b2,
         float* __restrict__ out) {
    extern __shared__ float sm[];
    float* W1c  = sm;                       // [c][HC]
    float* f0   = sm + HC * CC;             // 256
    float* f1   = f0 + CC;                  // 256
    float* os0  = f1 + CC;                  // 32
    float* os1  = os0 + DEC;                // 32
    float* red0 = os1 + DEC;                // 8
    float* red1 = red0 + 8;                 // 8

    int b0 = blockIdx.x * BPB;
    int b1i = b0 + 1;
    int t = threadIdx.x;

    // Preload W1 cache (one-time)
    for (int idx = t; idx < HC * CC; idx += 256) {
        int c = idx / HC, h = idx - c * HC;
        W1c[idx] = w1[c * HID + h];
    }
    int h0 = 2 * t;
    float b1a = b1[h0], b1b = b1[h0 + 1];
    float w2a = w2[h0], w2b = w2[h0 + 1];
    float b2v = b2[0];
    const float2* wg = (const float2*)w1;   // wg[c*256 + t] = w1[c][2t..2t+1]
    const float2* wc = (const float2*)W1c;  // wc[c*96  + t]
    __syncthreads();

    for (int i = 0; i < DEC; i++) {
        // feat = feat_enc + feedback from generated outputs
        float f0v = g_feat_enc[(b0 * DEC + i) * CC + t];
        float f1v = g_feat_enc[(b1i * DEC + i) * CC + t];
        for (int j = 0; j < i; j++) {
            float wv = g_WT_B[(i - 1 - j) * CC + t];
            f0v += wv * os0[j];
            f1v += wv * os1[j];
        }
        f0[t] = f0v;
        f1[t] = f1v;
        __syncthreads();

        // MLP1: thread t owns hidden columns h0, h0+1 for both batches
        float a00 = b1a, a01 = b1b;   // batch 0
        float a10 = b1a, a11 = b1b;   // batch 1
        if (t < HC / 2) {
            #pragma unroll 8
            for (int c = 0; c < CC; c++) {
                float fv0 = f0[c], fv1 = f1[c];
                float2 w = wc[c * (HC / 2) + t];
                a00 += fv0 * w.x; a01 += fv0 * w.y;
                a10 += fv1 * w.x; a11 += fv1 * w.y;
            }
        } else {
            #pragma unroll 8
            for (int c = 0; c < CC; c++) {
                float fv0 = f0[c], fv1 = f1[c];
                float2 w = wg[c * (HID / 2) + t];
                a00 += fv0 * w.x; a01 += fv0 * w.y;
                a10 += fv1 * w.x; a11 += fv1 * w.y;
            }
        }
        a00 = fmaxf(a00, 0.f); a01 = fmaxf(a01, 0.f);
        a10 = fmaxf(a10, 0.f); a11 = fmaxf(a11, 0.f);
        float po0 = a00 * w2a + a01 * w2b;
        float po1 = a10 * w2a + a11 * w2b;

        // Block reduction over H
        #pragma unroll
        for (int off = 16; off > 0; off >>= 1) {
            po0 += __shfl_down_sync(0xffffffffu, po0, off);
            po1 += __shfl_down_sync(0xffffffffu, po1, off);
        }
        if ((t & 31) == 0) { red0[t >> 5] = po0; red1[t >> 5] = po1; }
        __syncthreads();
        if (t == 0) {
            float o0 = b2v, o1 = b2v;
            #pragma unroll
            for (int wq = 0; wq < 8; wq++) { o0 += red0[wq]; o1 += red1[wq]; }
            os0[i] = o0; os1[i] = o1;
            out[b0 * DEC + i]  = o0;
            out[b1i * DEC + i] = o1;
        }
        __syncthreads();
    }
}

// ---------------------------------------------------------------------------
extern "C" void kernel_launch(void* const* d_in, const int* in_sizes, int n_in,
                              void* d_out, int out_size) {
    const float* x   = (const float*)d_in[0];  // [64,1,543]
    const float* c0w = (const float*)d_in[1];  // [256,1,2]
    const float* c0b = (const float*)d_in[2];  // [256]
    const float* cw  = (const float*)d_in[3];  // [7,256,256,2]
    const float* cb  = (const float*)d_in[4];  // [7,256]
    const float* w1  = (const float*)d_in[5];  // [256,512]
    const float* b1  = (const float*)d_in[6];  // [512]
    const float* w2  = (const float*)d_in[7];  // [512,1]
    const float* b2  = (const float*)d_in[8];  // [1]
    float* out = (float*)d_out;                // [64,32]

    k_init<<<256, 256>>>(c0w, c0b);
    int d = 2;
    for (int j = 0; j < 7; j++) {
        k_compose<<<dim3(8, 8), 256>>>(j & 1, cw + (size_t)j * CC * CC * 2,
                                       cb + j * CC, d);
        d <<= 1;
    }
    k_featenc<<<dim3(64, 4), 256>>>(x);

    const int dec_smem = (HC * CC + 2 * CC + 2 * DEC + 16) * (int)sizeof(float);
    cudaFuncSetAttribute(k_decode, cudaFuncAttributeMaxDynamicSharedMemorySize,
                         dec_smem);
    k_decode<<<BATCH / BPB, 256, dec_smem>>>(w1, b1, w2, b2, out);
}

// round 2
// speedup vs baseline: 1.8698x; 1.8698x over previous
#include <cuda_runtime.h>

#define CC    256
#define LAGS  256
#define BATCH 64
#define DEC   32
#define TTOT  543
#define HID   512
#define NBC   64      // blocks in fused compose kernel (all co-resident)

// Persistent scratch (no allocations allowed).
__device__ float g_PA[4 * LAGS * CC];   // split-k partial buffers (ping)
__device__ float g_PB[4 * LAGS * CC];   // (pong)
__device__ float g_W[LAGS * CC];        // final composed filter [tau][c]
__device__ float g_bA[CC];
__device__ float g_bB[CC];
__device__ float g_feat_enc[BATCH * DEC * CC];
__device__ float g_E[BATCH * DEC * HID];  // feat_enc @ W1 + b1
__device__ float g_G[31 * HID];           // Weff[:,d]^T @ W1, d=0..30
__device__ unsigned g_bar_count;          // zero-init; barrier resets to 0
__device__ volatile unsigned g_bar_gen;

__device__ __forceinline__ void gridbar() {
    __syncthreads();
    if (threadIdx.x == 0) {
        unsigned gen = g_bar_gen;
        __threadfence();
        if (atomicAdd(&g_bar_count, 1u) == NBC - 1) {
            g_bar_count = 0;
            __threadfence();
            g_bar_gen = gen + 1;
        } else {
            while (g_bar_gen == gen) { }
            __threadfence();
        }
    }
    __syncthreads();
}

// ---------------------------------------------------------------------------
// Fused: init + 7 compose layers (split-k partials, grid barrier) + final
// reduce + G = Weff[:,0..30]^T @ W1.
// Tile: 64 tau x 64 co, k-range 64 per block, 4x4 micro-tile, warps 2x4.
// ---------------------------------------------------------------------------
__global__ void __launch_bounds__(256)
k_compose_all(const float* __restrict__ c0w, const float* __restrict__ c0b,
              const float* __restrict__ cw,  const float* __restrict__ cb,
              const float* __restrict__ w1) {
    __shared__ float As[16][68], Ss[16][68], B0s[16][68], B1s[16][68];
    __shared__ float wt[256];
    int b = blockIdx.x, t = threadIdx.x;

    // ---- init: zero both partial buffers, then conv0 taps into PA slot 0 ----
    {
        int base = b * 8192;   // 64 blocks * 8192 = 524288 = 2 * 4 * 65536
        for (int e = t; e < 8192; e += 256) {
            int idx = base + e;
            if (idx < 4 * LAGS * CC) g_PA[idx] = 0.f;
            else                     g_PB[idx - 4 * LAGS * CC] = 0.f;
        }
        __syncthreads();
        if (b == 0) {
            g_PA[t]      = c0w[t * 2 + 1];   // tau 0
            g_PA[CC + t] = c0w[t * 2 + 0];   // tau 1
            g_bA[t]      = c0b[t];
        }
    }
    gridbar();

    // ---- 7 layers ----
    int d = 2;
    for (int j = 0; j < 7; j++) {
        const float* Ps   = (j & 1) ? g_PB : g_PA;
        float*       Pd   = (j & 1) ? g_PA : g_PB;
        const float* srcb = (j & 1) ? g_bB : g_bA;
        float*       dstb = (j & 1) ? g_bA : g_bB;
        const float* w = cw + (size_t)j * CC * CC * 2;
        int R  = 4 << j;               // taps after this layer
        int TT = (R + 63) >> 6;        // tau tiles (1,1,1,1,1,2,4)
        int nuse = TT * 16;            // tiles * 4 co * 4 ksplit
        if (b < nuse) {
            int kp = b & 3, cot = (b >> 2) & 3, taut = b >> 4;
            int tau0 = taut * 64, co0 = cot * 64, k0 = kp * 64;
            int wid = t >> 5, lane = t & 31;
            int ta  = (wid >> 2) * 32 + (lane & 7) * 4;   // tau offset in tile
            int cb2 = (wid & 3) * 16 + (lane >> 3) * 4;   // co offset in tile
            float acc[4][4];
            #pragma unroll
            for (int ii = 0; ii < 4; ii++)
                #pragma unroll
                for (int jj = 0; jj < 4; jj++) acc[ii][jj] = 0.f;
            const float2* wp2 = (const float2*)w;
            for (int kc = 0; kc < 64; kc += 16) {
                __syncthreads();
                #pragma unroll
                for (int e = 0; e < 4; e++) {
                    int idx = e * 256 + t;
                    int kk = idx & 15, r = idx >> 4;
                    int ci = k0 + kc + kk;
                    int ra = (tau0 + r) * CC + ci;
                    As[kk][r] = Ps[ra] + Ps[65536 + ra] + Ps[131072 + ra]
                              + Ps[196608 + ra];
                    int ts = tau0 + r - d;
                    float vs = 0.f;
                    if (ts >= 0) {
                        int rs = ts * CC + ci;
                        vs = Ps[rs] + Ps[65536 + rs] + Ps[131072 + rs]
                           + Ps[196608 + rs];
                    }
                    Ss[kk][r] = vs;
                    float2 wv = wp2[(size_t)(co0 + r) * CC + ci];
                    B0s[kk][r] = wv.x;
                    B1s[kk][r] = wv.y;
                }
                __syncthreads();
                #pragma unroll
                for (int kk = 0; kk < 16; kk++) {
                    float4 av  = *(const float4*)&As[kk][ta];
                    float4 sv  = *(const float4*)&Ss[kk][ta];
                    float4 b1v = *(const float4*)&B1s[kk][cb2];
                    float4 b0v = *(const float4*)&B0s[kk][cb2];
                    float a_[4] = {av.x, av.y, av.z, av.w};
                    float s_[4] = {sv.x, sv.y, sv.z, sv.w};
                    float p_[4] = {b1v.x, b1v.y, b1v.z, b1v.w};
                    float q_[4] = {b0v.x, b0v.y, b0v.z, b0v.w};
                    #pragma unroll
                    for (int ii = 0; ii < 4; ii++)
                        #pragma unroll
                        for (int jj = 0; jj < 4; jj++)
                            acc[ii][jj] += a_[ii] * p_[jj] + s_[ii] * q_[jj];
                }
            }
            float* dstp = Pd + kp * 65536;
            #pragma unroll
            for (int ii = 0; ii < 4; ii++) {
                float4 v = make_float4(acc[ii][0], acc[ii][1],
                                       acc[ii][2], acc[ii][3]);
                *(float4*)&dstp[(tau0 + ta + ii) * CC + co0 + cb2] = v;
            }
        }
        // bias chain: blocks 60..63 handle 64 co each
        if (b >= 60 && t < 64) {
            int co = (b - 60) * 64 + t;
            float acc = cb[(size_t)j * CC + co];
            const float2* wp2b = (const float2*)w;
            #pragma unroll 4
            for (int ci = 0; ci < CC; ci++) {
                float2 wv = wp2b[(size_t)co * CC + ci];
                acc += (wv.x + wv.y) * srcb[ci];
            }
            dstb[co] = acc;
        }
        gridbar();
        d <<= 1;
    }

    // ---- reduce final partials (in PB after 7 layers) to g_W ----
    {
        int base = b * 1024;
        for (int e = t; e < 1024; e += 256) {
            int idx = base + e;
            g_W[idx] = g_PB[idx] + g_PB[65536 + idx] + g_PB[131072 + idx]
                     + g_PB[196608 + idx];
        }
    }
    gridbar();

    // ---- G[d,h] = sum_c Weff[c,d] * W1[c,h], d = 0..30 ----
    if (b < 62) {
        int dl = b >> 1, hh = (b & 1) * 256;
        wt[t] = g_W[dl * CC + t];
        __syncthreads();
        float acc = 0.f;
        #pragma unroll 8
        for (int c = 0; c < CC; c++)
            acc += wt[c] * w1[(size_t)c * HID + hh + t];
        g_G[dl * HID + hh + t] = acc;
    }
}

// ---------------------------------------------------------------------------
// Encoder precompute (unchanged from R1, reads g_W / g_bB):
//   feat_enc[b,i,c] = beff[c] + sum_{tau>=i} Weff[c,tau] * x[b, 511+i-tau]
// ---------------------------------------------------------------------------
__global__ void k_featenc(const float* __restrict__ x) {
    __shared__ float xs[256];
    __shared__ float Ws[32][65];
    int b = blockIdx.x, ct = blockIdx.y;
    int t = threadIdx.x;
    xs[t] = x[b * TTOT + 256 + t];
    int c_l = t & 63, ig = t >> 6;
    float acc[8] = {0.f, 0.f, 0.f, 0.f, 0.f, 0.f, 0.f, 0.f};

    for (int tc = 0; tc < LAGS; tc += 32) {
        __syncthreads();
        #pragma unroll
        for (int e = 0; e < 8; e++) {
            int li = e * 256 + t;
            int tt = li >> 6, cc = li & 63;
            Ws[tt][cc] = g_W[(tc + tt) * CC + ct * 64 + cc];
        }
        __syncthreads();
        for (int tt = 0; tt < 32; tt++) {
            int tau = tc + tt;
            float wv = Ws[tt][c_l];
            #pragma unroll
            for (int r = 0; r < 8; r++) {
                int i = ig * 8 + r;
                if (tau >= i) acc[r] += wv * xs[255 + i - tau];
            }
        }
    }
    float bv = g_bB[ct * 64 + c_l];
    #pragma unroll
    for (int r = 0; r < 8; r++) {
        int i = ig * 8 + r;
        g_feat_enc[(b * DEC + i) * CC + ct * 64 + c_l] = acc[r] + bv;
    }
}

// ---------------------------------------------------------------------------
// E = feat_enc[2048,256] @ W1[256,512] + b1  (64x64 tiles, 4x4 micro)
// ---------------------------------------------------------------------------
__global__ void __launch_bounds__(256)
k_E(const float* __restrict__ w1, const float* __restrict__ b1) {
    __shared__ float As[16][68], Bs[16][68];
    int m0 = blockIdx.y * 64, n0 = blockIdx.x * 64;
    int t = threadIdx.x;
    int wid = t >> 5, lane = t & 31;
    int mi = (wid >> 2) * 32 + (lane & 7) * 4;
    int ni = (wid & 3) * 16 + (lane >> 3) * 4;
    float acc[4][4];
    #pragma unroll
    for (int ii = 0; ii < 4; ii++)
        #pragma unroll
        for (int jj = 0; jj < 4; jj++) acc[ii][jj] = 0.f;
    for (int kc = 0; kc < CC; kc += 16) {
        __syncthreads();
        #pragma unroll
        for (int e = 0; e < 4; e++) {
            int idx = e * 256 + t;
            int kk = idx & 15, m = idx >> 4;
            As[kk][m] = g_feat_enc[(size_t)(m0 + m) * CC + kc + kk];
            int n = idx & 63, kb = idx >> 6;
            Bs[kb][n] = w1[(size_t)(kc + kb) * HID + n0 + n];
        }
        __syncthreads();
        #pragma unroll
        for (int kk = 0; kk < 16; kk++) {
            float4 av = *(const float4*)&As[kk][mi];
            float4 bv = *(const float4*)&Bs[kk][ni];
            float a_[4] = {av.x, av.y, av.z, av.w};
            float b_[4] = {bv.x, bv.y, bv.z, bv.w};
            #pragma unroll
            for (int ii = 0; ii < 4; ii++)
                #pragma unroll
                for (int jj = 0; jj < 4; jj++)
                    acc[ii][jj] += a_[ii] * b_[jj];
        }
    }
    float4 bb = *(const float4*)&b1[n0 + ni];
    #pragma unroll
    for (int ii = 0; ii < 4; ii++) {
        float4 v = make_float4(acc[ii][0] + bb.x, acc[ii][1] + bb.y,
                               acc[ii][2] + bb.z, acc[ii][3] + bb.w);
        *(float4*)&g_E[(size_t)(m0 + mi + ii) * HID + n0 + ni] = v;
    }
}

// ---------------------------------------------------------------------------
// Autoregressive decode in the G-basis: a[b,i,h] = E[b,i,h] + sum_j G[i-1-j,h] o_j
// 16 blocks x 4 batches; G fully SMEM-resident; ~i*8 FMA/thread/step.
// ---------------------------------------------------------------------------
__global__ void __launch_bounds__(256)
k_decode(const float* __restrict__ w2, const float* __restrict__ b2,
         float* __restrict__ out) {
    extern __shared__ float sm[];
    float* Gs  = sm;                 // 31*512
    float* os4 = Gs + 31 * HID;      // DEC*4 (float4 per step: o for 4 batches)
    float* red = os4 + DEC * 4;      // 4*8
    int t = threadIdx.x;
    int b0 = blockIdx.x * 4;
    for (int e = t; e < 31 * HID; e += 256) Gs[e] = g_G[e];
    float w2a = w2[2 * t], w2b = w2[2 * t + 1];
    float b2v = b2[0];
    __syncthreads();
    const float2* Ef = (const float2*)g_E;
    const float2* G2 = (const float2*)Gs;
    int wid = t >> 5, lane = t & 31;
    for (int i = 0; i < DEC; i++) {
        float2 a0 = Ef[(size_t)((b0 + 0) * DEC + i) * 256 + t];
        float2 a1 = Ef[(size_t)((b0 + 1) * DEC + i) * 256 + t];
        float2 a2 = Ef[(size_t)((b0 + 2) * DEC + i) * 256 + t];
        float2 a3 = Ef[(size_t)((b0 + 3) * DEC + i) * 256 + t];
        for (int j = 0; j < i; j++) {
            float2 g = G2[(i - 1 - j) * 256 + t];
            float4 ov = *(const float4*)&os4[j * 4];
            a0.x += g.x * ov.x; a0.y += g.y * ov.x;
            a1.x += g.x * ov.y; a1.y += g.y * ov.y;
            a2.x += g.x * ov.z; a2.y += g.y * ov.z;
            a3.x += g.x * ov.w; a3.y += g.y * ov.w;
        }
        float p0 = fmaxf(a0.x, 0.f) * w2a + fmaxf(a0.y, 0.f) * w2b;
        float p1 = fmaxf(a1.x, 0.f) * w2a + fmaxf(a1.y, 0.f) * w2b;
        float p2 = fmaxf(a2.x, 0.f) * w2a + fmaxf(a2.y, 0.f) * w2b;
        float p3 = fmaxf(a3.x, 0.f) * w2a + fmaxf(a3.y, 0.f) * w2b;
        #pragma unroll
        for (int off = 16; off > 0; off >>= 1) {
            p0 += __shfl_down_sync(0xffffffffu, p0, off);
            p1 += __shfl_down_sync(0xffffffffu, p1, off);
            p2 += __shfl_down_sync(0xffffffffu, p2, off);
            p3 += __shfl_down_sync(0xffffffffu, p3, off);
        }
        if (lane == 0) {
            red[0 * 8 + wid] = p0; red[1 * 8 + wid] = p1;
            red[2 * 8 + wid] = p2; red[3 * 8 + wid] = p3;
        }
        __syncthreads();
        if (t < 4) {
            float o = b2v;
            #pragma unroll
            for (int q = 0; q < 8; q++) o += red[t * 8 + q];
            os4[i * 4 + t] = o;
            out[(b0 + t) * DEC + i] = o;
        }
        __syncthreads();
    }
}

// ---------------------------------------------------------------------------
extern "C" void kernel_launch(void* const* d_in, const int* in_sizes, int n_in,
                              void* d_out, int out_size) {
    const float* x   = (const float*)d_in[0];  // [64,1,543]
    const float* c0w = (const float*)d_in[1];  // [256,1,2]
    const float* c0b = (const float*)d_in[2];  // [256]
    const float* cw  = (const float*)d_in[3];  // [7,256,256,2]
    const float* cb  = (const float*)d_in[4];  // [7,256]
    const float* w1  = (const float*)d_in[5];  // [256,512]
    const float* b1  = (const float*)d_in[6];  // [512]
    const float* w2  = (const float*)d_in[7];  // [512,1]
    const float* b2  = (const float*)d_in[8];  // [1]
    float* out = (float*)d_out;                // [64,32]

    k_compose_all<<<NBC, 256>>>(c0w, c0b, cw, cb, w1);
    k_featenc<<<dim3(64, 4), 256>>>(x);
    k_E<<<dim3(8, 32), 256>>>(w1, b1);

    const int dec_smem = (31 * HID + DEC * 4 + 32) * (int)sizeof(float);
    cudaFuncSetAttribute(k_decode, cudaFuncAttributeMaxDynamicSharedMemorySize,
                         dec_smem);
    k_decode<<<BATCH / 4, 256, dec_smem>>>(w2, b2, out);
}

// round 3
// speedup vs baseline: 1.9078x; 1.0204x over previous
#include <cuda_runtime.h>

#define CC    256
#define LAGS  256
#define BATCH 64
#define DEC   32
#define TTOT  543
#define HID   512
#define NBC   64

// Persistent scratch (no allocations allowed).
__device__ float g_PA[4 * LAGS * CC];
__device__ float g_PB[4 * LAGS * CC];
__device__ float g_W[LAGS * CC];          // composed filter [tau][c]
__device__ float g_bA[CC];
__device__ float g_bB[CC];
__device__ float g_GH[LAGS * HID];        // GH[tau][h] = sum_c Weff[c,tau]*W1[c,h]
__device__ float g_Ec[HID];               // b1 + beff^T W1
__device__ float g_E[BATCH * DEC * HID];
__device__ unsigned g_bar_count;
__device__ volatile unsigned g_bar_gen;

__device__ __forceinline__ void gridbar() {
    __syncthreads();
    if (threadIdx.x == 0) {
        unsigned gen = g_bar_gen;
        __threadfence();
        if (atomicAdd(&g_bar_count, 1u) == NBC - 1) {
            g_bar_count = 0;
            __threadfence();
            g_bar_gen = gen + 1;
        } else {
            while (g_bar_gen == gen) { }
            __threadfence();
        }
    }
    __syncthreads();
}

__device__ __forceinline__ void pf_l2(const void* p) {
    asm volatile("prefetch.global.L2 [%0];" :: "l"(p));
}

// ---------------------------------------------------------------------------
// Fused: init + 7 compose layers + reduce + GH GEMM + Econst.
// ---------------------------------------------------------------------------
__global__ void __launch_bounds__(256)
k_compose_all(const float* __restrict__ c0w, const float* __restrict__ c0b,
              const float* __restrict__ cw,  const float* __restrict__ cb,
              const float* __restrict__ w1,  const float* __restrict__ b1) {
    __shared__ float As[16][68], Ss[16][68], B0s[16][68], B1s[16][68];
    __shared__ float Wg[16][33], w1s[32][132];
    int b = blockIdx.x, t = threadIdx.x;

    // ---- init: zero partial buffers; conv0 taps into PA slot 0 ----
    {
        int base = b * 8192;
        for (int e = t; e < 8192; e += 256) {
            int idx = base + e;
            if (idx < 4 * LAGS * CC) g_PA[idx] = 0.f;
            else                     g_PB[idx - 4 * LAGS * CC] = 0.f;
        }
        __syncthreads();
        if (b == 0) {
            g_PA[t]      = c0w[t * 2 + 1];
            g_PA[CC + t] = c0w[t * 2 + 0];
            g_bA[t]      = c0b[t];
        }
    }
    gridbar();

    // ---- 7 layers ----
    int d = 2;
    for (int j = 0; j < 7; j++) {
        // prefetch next layer weights / w1 into L2 (overlaps this layer)
        if (j < 6 && (t & 3) == 0) {
            const float* nw = cw + (size_t)(j + 1) * CC * CC * 2;
            int line = b * 64 + (t >> 2);           // 4096 lines of 128B
            pf_l2(nw + (size_t)line * 32);
        }
        if (j == 0 && (t & 3) == 1) {
            int line = b * 64 + (t >> 2);
            pf_l2(w1 + (size_t)line * 32);
        }

        const float* Ps   = (j & 1) ? g_PB : g_PA;
        float*       Pd   = (j & 1) ? g_PA : g_PB;
        const float* srcb = (j & 1) ? g_bB : g_bA;
        float*       dstb = (j & 1) ? g_bA : g_bB;
        const float* w = cw + (size_t)j * CC * CC * 2;
        int R  = 4 << j;
        int TT = (R + 63) >> 6;
        int nuse = TT * 16;
        if (b < nuse) {
            int kp = b & 3, cot = (b >> 2) & 3, taut = b >> 4;
            int tau0 = taut * 64, co0 = cot * 64, k0 = kp * 64;
            int wid = t >> 5, lane = t & 31;
            int ta  = (wid >> 2) * 32 + (lane & 7) * 4;
            int cb2 = (wid & 3) * 16 + (lane >> 3) * 4;
            float acc[4][4];
            #pragma unroll
            for (int ii = 0; ii < 4; ii++)
                #pragma unroll
                for (int jj = 0; jj < 4; jj++) acc[ii][jj] = 0.f;
            const float2* wp2 = (const float2*)w;
            for (int kc = 0; kc < 64; kc += 16) {
                __syncthreads();
                #pragma unroll
                for (int e = 0; e < 4; e++) {
                    int idx = e * 256 + t;
                    int kk = idx & 15, r = idx >> 4;
                    int ci = k0 + kc + kk;
                    int ra = (tau0 + r) * CC + ci;
                    As[kk][r] = Ps[ra] + Ps[65536 + ra] + Ps[131072 + ra]
                              + Ps[196608 + ra];
                    int ts = tau0 + r - d;
                    float vs = 0.f;
                    if (ts >= 0) {
                        int rs = ts * CC + ci;
                        vs = Ps[rs] + Ps[65536 + rs] + Ps[131072 + rs]
                           + Ps[196608 + rs];
                    }
                    Ss[kk][r] = vs;
                    float2 wv = wp2[(size_t)(co0 + r) * CC + ci];
                    B0s[kk][r] = wv.x;
                    B1s[kk][r] = wv.y;
                }
                __syncthreads();
                #pragma unroll
                for (int kk = 0; kk < 16; kk++) {
                    float4 av  = *(const float4*)&As[kk][ta];
                    float4 sv  = *(const float4*)&Ss[kk][ta];
                    float4 b1v = *(const float4*)&B1s[kk][cb2];
                    float4 b0v = *(const float4*)&B0s[kk][cb2];
                    float a_[4] = {av.x, av.y, av.z, av.w};
                    float s_[4] = {sv.x, sv.y, sv.z, sv.w};
                    float p_[4] = {b1v.x, b1v.y, b1v.z, b1v.w};
                    float q_[4] = {b0v.x, b0v.y, b0v.z, b0v.w};
                    #pragma unroll
                    for (int ii = 0; ii < 4; ii++)
                        #pragma unroll
                        for (int jj = 0; jj < 4; jj++)
                            acc[ii][jj] += a_[ii] * p_[jj] + s_[ii] * q_[jj];
                }
            }
            float* dstp = Pd + kp * 65536;
            #pragma unroll
            for (int ii = 0; ii < 4; ii++) {
                float4 v = make_float4(acc[ii][0], acc[ii][1],
                                       acc[ii][2], acc[ii][3]);
                *(float4*)&dstp[(tau0 + ta + ii) * CC + co0 + cb2] = v;
            }
        }
        if (b >= 60 && t < 64) {
            int co = (b - 60) * 64 + t;
            float acc = cb[(size_t)j * CC + co];
            const float2* wp2b = (const float2*)w;
            #pragma unroll 4
            for (int ci = 0; ci < CC; ci++) {
                float2 wv = wp2b[(size_t)co * CC + ci];
                acc += (wv.x + wv.y) * srcb[ci];
            }
            dstb[co] = acc;
        }
        gridbar();
        d <<= 1;
    }

    // ---- reduce final partials (in PB) to g_W ----
    {
        int base = b * 1024;
        for (int e = t; e < 1024; e += 256) {
            int idx = base + e;
            g_W[idx] = g_PB[idx] + g_PB[65536 + idx] + g_PB[131072 + idx]
                     + g_PB[196608 + idx];
        }
    }
    gridbar();

    // ---- Econst[h] = b1[h] + sum_c beff[c]*W1[c,h] (blocks 60..63) ----
    if (b >= 60 && t < 128) {
        int h = (b - 60) * 128 + t;
        float acc = b1[h];
        #pragma unroll 4
        for (int c = 0; c < CC; c++)
            acc += g_bB[c] * w1[(size_t)c * HID + h];
        g_Ec[h] = acc;
    }

    // ---- GH[tau0..+15][h0..+127] = Weff^T(tile) @ W1(tile) ----
    {
        int tau0 = (b >> 2) * 16, h0 = (b & 3) * 128;
        int r = t >> 4, h8 = (t & 15) * 8;
        float acc[8];
        #pragma unroll
        for (int q = 0; q < 8; q++) acc[q] = 0.f;
        for (int cc2 = 0; cc2 < CC; cc2 += 32) {
            __syncthreads();
            #pragma unroll
            for (int e = 0; e < 2; e++) {
                int idx = e * 256 + t;
                int rr = idx >> 5, c = idx & 31;
                Wg[rr][c] = g_W[(tau0 + rr) * CC + cc2 + c];
            }
            #pragma unroll
            for (int e = 0; e < 16; e++) {
                int idx = e * 256 + t;
                int row = idx >> 7, col = idx & 127;
                w1s[row][col] = w1[(size_t)(cc2 + row) * HID + h0 + col];
            }
            __syncthreads();
            #pragma unroll
            for (int c = 0; c < 32; c++) {
                float wv = Wg[r][c];
                #pragma unroll
                for (int q = 0; q < 8; q++)
                    acc[q] += wv * w1s[c][h8 + q];
            }
        }
        #pragma unroll
        for (int q = 0; q < 8; q++)
            g_GH[(tau0 + r) * HID + h0 + h8 + q] = acc[q];
    }
}

// ---------------------------------------------------------------------------
// E[b,i,h] = Econst[h] + sum_{tau} GH[tau,h] * xs[255+i-tau]
// (xs zero-padded above 255 so tau<i terms vanish; no predicates).
// Grid (64 b, 4 htiles), 256 thr: h_l = t&127, ig = t>>7 (16 i each).
// ---------------------------------------------------------------------------
__global__ void __launch_bounds__(256)
k_E(const float* __restrict__ x) {
    __shared__ float xs[288];
    __shared__ float GHs[32][132];
    int b = blockIdx.x, ht = blockIdx.y, t = threadIdx.x;
    int h0 = ht * 128;
    xs[t] = x[b * TTOT + 256 + t];
    if (t < 32) xs[256 + t] = 0.f;
    int h_l = t & 127, ig = t >> 7;
    float acc[16];
    #pragma unroll
    for (int r = 0; r < 16; r++) acc[r] = 0.f;

    for (int tc = 0; tc < LAGS; tc += 32) {
        __syncthreads();
        #pragma unroll
        for (int e = 0; e < 16; e++) {
            int idx = e * 256 + t;
            int row = idx >> 7, col = idx & 127;
            GHs[row][col] = g_GH[(tc + row) * HID + h0 + col];
        }
        __syncthreads();
        float xw[47];
        int base = 255 + ig * 16 - tc - 31;
        #pragma unroll
        for (int q = 0; q < 47; q++) xw[q] = xs[base + q];
        #pragma unroll
        for (int tt = 0; tt < 32; tt++) {
            float wv = GHs[tt][h_l];
            #pragma unroll
            for (int r = 0; r < 16; r++)
                acc[r] += wv * xw[r + 31 - tt];
        }
    }
    float ec = g_Ec[h0 + h_l];
    #pragma unroll
    for (int r = 0; r < 16; r++)
        g_E[(size_t)(b * DEC + ig * 16 + r) * HID + h0 + h_l] = acc[r] + ec;
}

// ---------------------------------------------------------------------------
// Decode v3: 1 batch/block (64 blocks), E register-resident, eager updates.
// ---------------------------------------------------------------------------
__global__ void __launch_bounds__(256, 1)
k_decode(const float* __restrict__ w2, const float* __restrict__ b2,
         float* __restrict__ out) {
    extern __shared__ float sm[];
    float* Gs  = sm;                 // 31*512
    float* red = sm + 31 * HID;      // 16 (double-buffered 2x8)
    int t = threadIdx.x, b = blockIdx.x;
    int wid = t >> 5, lane = t & 31;
    for (int e = t; e < 31 * HID; e += 256) Gs[e] = g_GH[e];
    float2 a[DEC];
    const float2* Ef = (const float2*)(g_E + (size_t)b * DEC * HID);
    #pragma unroll
    for (int i = 0; i < DEC; i++) a[i] = Ef[i * 256 + t];
    float2 w2v = ((const float2*)w2)[t];
    float b2v = b2[0];
    __syncthreads();
    const float2* G2 = (const float2*)Gs;
    #pragma unroll
    for (int i = 0; i < DEC; i++) {
        float p = fmaxf(a[i].x, 0.f) * w2v.x + fmaxf(a[i].y, 0.f) * w2v.y;
        #pragma unroll
        for (int off = 16; off > 0; off >>= 1)
            p += __shfl_down_sync(0xffffffffu, p, off);
        if (lane == 0) red[(i & 1) * 8 + wid] = p;
        __syncthreads();
        float o = b2v;
        #pragma unroll
        for (int q = 0; q < 8; q++) o += red[(i & 1) * 8 + q];
        if (t == 0) out[b * DEC + i] = o;
        #pragma unroll
        for (int ii = i + 1; ii < DEC; ii++) {
            float2 g = G2[(ii - 1 - i) * 256 + t];
            a[ii].x += g.x * o;
            a[ii].y += g.y * o;
        }
    }
}

// ---------------------------------------------------------------------------
extern "C" void kernel_launch(void* const* d_in, const int* in_sizes, int n_in,
                              void* d_out, int out_size) {
    const float* x   = (const float*)d_in[0];
    const float* c0w = (const float*)d_in[1];
    const float* c0b = (const float*)d_in[2];
    const float* cw  = (const float*)d_in[3];
    const float* cb  = (const float*)d_in[4];
    const float* w1  = (const float*)d_in[5];
    const float* b1  = (const float*)d_in[6];
    const float* w2  = (const float*)d_in[7];
    const float* b2  = (const float*)d_in[8];
    float* out = (float*)d_out;

    k_compose_all<<<NBC, 256>>>(c0w, c0b, cw, cb, w1, b1);
    k_E<<<dim3(64, 4), 256>>>(x);

    const int dec_smem = (31 * HID + 16) * (int)sizeof(float);
    cudaFuncSetAttribute(k_decode, cudaFuncAttributeMaxDynamicSharedMemorySize,
                         dec_smem);
    k_decode<<<BATCH, 256, dec_smem>>>(w2, b2, out);
}

// round 4
// speedup vs baseline: 2.2056x; 1.1561x over previous
#include <cuda_runtime.h>

#define CC    256
#define LAGS  256
#define BATCH 64
#define DEC   32
#define TTOT  543
#define HID   512
#define NBC   256
#define NGRP  16

typedef unsigned long long ull;

// Persistent scratch (no allocations allowed).
__device__ float g_PA[4 * LAGS * CC];
__device__ float g_PB[4 * LAGS * CC];
__device__ float g_bA[CC];
__device__ float g_bB[CC];
__device__ float g_GH[LAGS * HID];   // GH[tau][h] = sum_c Weff[c,tau]*W1[c,h]
__device__ float g_Ec[HID];          // b1 + beff^T W1
__device__ float g_E[BATCH * DEC * HID];
__device__ unsigned g_cnt[NGRP * 32];
__device__ unsigned g_root;
__device__ volatile unsigned g_gen;

__device__ __forceinline__ ull pk2(float x, float y) {
    ull r;
    asm("mov.b64 %0, {%1, %2};" : "=l"(r) : "f"(x), "f"(y));
    return r;
}
__device__ __forceinline__ void upk2(float& x, float& y, ull v) {
    asm("mov.b64 {%0, %1}, %2;" : "=f"(x), "=f"(y) : "l"(v));
}
__device__ __forceinline__ ull fma2(ull a, ull b, ull c) {
    ull d;
    asm("fma.rn.f32x2 %0, %1, %2, %3;" : "=l"(d) : "l"(a), "l"(b), "l"(c));
    return d;
}

__device__ __forceinline__ void gridbar(int b) {
    __syncthreads();
    if (threadIdx.x == 0) {
        unsigned gen = g_gen;
        __threadfence();
        bool last = false;
        if (atomicAdd(&g_cnt[(b >> 4) * 32], 1u) == 15u) {
            if (atomicAdd(&g_root, 1u) == NGRP - 1) last = true;
        }
        if (last) {
            #pragma unroll
            for (int q = 0; q < NGRP; q++) g_cnt[q * 32] = 0u;
            g_root = 0u;
            __threadfence();
            g_gen = gen + 1;
        } else {
            while (g_gen == gen) { }
            __threadfence();
        }
    }
    __syncthreads();
}

// ---------------------------------------------------------------------------
// Persistent compose: init + 7 layers (16tau x 64co tiles, k-split 4, spread
// over up to 256 blocks) + GH (reads partials directly) + Econst.
// ---------------------------------------------------------------------------
__global__ void __launch_bounds__(256, 2)
k_compose_all(const float* __restrict__ c0w, const float* __restrict__ c0b,
              const float* __restrict__ cw,  const float* __restrict__ cb,
              const float* __restrict__ w1,  const float* __restrict__ b1) {
    __shared__ float As[16][17], Ss[16][17];
    __shared__ float B0s[16][68], B1s[16][68];
    __shared__ float Wgs[16][33], w1s[32][34], ecs[8][33];
    int b = blockIdx.x, t = threadIdx.x;

    // ---- init: zero partial buffers; conv0 taps into PA slot 0 ----
    {
        int base = b * 2048;
        #pragma unroll
        for (int e = 0; e < 8; e++) {
            int idx = base + e * 256 + t;
            if (idx < 4 * LAGS * CC) g_PA[idx] = 0.f;
            else                     g_PB[idx - 4 * LAGS * CC] = 0.f;
        }
        __syncthreads();
        if (b == 0) {
            g_PA[t]      = c0w[t * 2 + 1];   // tau 0
            g_PA[CC + t] = c0w[t * 2 + 0];   // tau 1
            g_bA[t]      = c0b[t];
        }
    }
    gridbar(b);

    // ---- 7 layers ----
    int d = 2;
    for (int j = 0; j < 7; j++) {
        const float* Ps   = (j & 1) ? g_PB : g_PA;
        float*       Pd   = (j & 1) ? g_PA : g_PB;
        const float* srcb = (j & 1) ? g_bB : g_bA;
        float*       dstb = (j & 1) ? g_bA : g_bB;
        const float* w = cw + (size_t)j * CC * CC * 2;
        int R  = 4 << j;
        int TT = (R + 15) >> 4;          // 1,1,1,2,4,8,16
        int nuse = TT * 16;
        if (b < nuse) {
            int kp = b & 3, cot = (b >> 2) & 3, taut = b >> 4;
            int tau0 = taut * 16, co0 = cot * 64, k0 = kp * 64;
            int tl  = t & 15;            // tau within tile
            int col = (t >> 4) * 4;      // co within tile (4 each)
            ull acc0 = 0ull, acc1 = 0ull;
            const float2* wp2 = (const float2*)w;
            for (int kc = 0; kc < 64; kc += 16) {
                __syncthreads();
                {
                    int kk = t & 15, r = t >> 4;
                    int ci = k0 + kc + kk;
                    int ra = (tau0 + r) * CC + ci;
                    As[kk][r] = Ps[ra] + Ps[65536 + ra] + Ps[131072 + ra]
                              + Ps[196608 + ra];
                    int ts = tau0 + r - d;
                    float vs = 0.f;
                    if (ts >= 0) {
                        int rs = ts * CC + ci;
                        vs = Ps[rs] + Ps[65536 + rs] + Ps[131072 + rs]
                           + Ps[196608 + rs];
                    }
                    Ss[kk][r] = vs;
                    int ci_l = t & 15, cw_l = t >> 4;
                    #pragma unroll
                    for (int p = 0; p < 4; p++) {
                        int co = p * 16 + cw_l;
                        float2 wv = wp2[(size_t)(co0 + co) * CC + k0 + kc + ci_l];
                        B0s[ci_l][co] = wv.x;
                        B1s[ci_l][co] = wv.y;
                    }
                }
                __syncthreads();
                #pragma unroll
                for (int kk = 0; kk < 16; kk++) {
                    float a = As[kk][tl], s = Ss[kk][tl];
                    ull a2 = pk2(a, a), s2 = pk2(s, s);
                    ull p0 = *(const ull*)&B1s[kk][col];
                    ull p1 = *(const ull*)&B1s[kk][col + 2];
                    ull q0 = *(const ull*)&B0s[kk][col];
                    ull q1 = *(const ull*)&B0s[kk][col + 2];
                    acc0 = fma2(a2, p0, acc0);
                    acc0 = fma2(s2, q0, acc0);
                    acc1 = fma2(a2, p1, acc1);
                    acc1 = fma2(s2, q1, acc1);
                }
            }
            float c0, c1, c2, c3;
            upk2(c0, c1, acc0);
            upk2(c2, c3, acc1);
            float4 v = make_float4(c0, c1, c2, c3);
            *(float4*)&Pd[kp * 65536 + (tau0 + tl) * CC + co0 + col] = v;
        }
        // bias chain: blocks 252..255, 64 co each
        if (b >= 252 && t < 64) {
            int co = (b - 252) * 64 + t;
            float acc = cb[(size_t)j * CC + co];
            const float2* wp2b = (const float2*)w;
            #pragma unroll 4
            for (int ci = 0; ci < CC; ci++) {
                float2 wv = wp2b[(size_t)co * CC + ci];
                acc += (wv.x + wv.y) * srcb[ci];
            }
            dstb[co] = acc;
        }
        gridbar(b);
        d <<= 1;
    }

    // ---- GH[tau0..+15][h0..+31] from final partials (in g_PB) ----
    {
        int tau0 = (b >> 4) * 16, h0 = (b & 15) * 32;
        int tg = t >> 4, h2 = (t & 15) * 2;
        ull acc = 0ull;
        for (int cc2 = 0; cc2 < CC; cc2 += 32) {
            __syncthreads();
            #pragma unroll
            for (int e = 0; e < 2; e++) {
                int idx = e * 256 + t;
                int tr = idx >> 5, cl = idx & 31;
                int ra = (tau0 + tr) * CC + cc2 + cl;
                Wgs[tr][cl] = g_PB[ra] + g_PB[65536 + ra] + g_PB[131072 + ra]
                            + g_PB[196608 + ra];
            }
            #pragma unroll
            for (int e = 0; e < 4; e++) {
                int idx = e * 256 + t;
                int cr = idx >> 5, hl = idx & 31;
                w1s[cr][hl] = w1[(size_t)(cc2 + cr) * HID + h0 + hl];
            }
            __syncthreads();
            #pragma unroll
            for (int ci = 0; ci < 32; ci++) {
                float wv = Wgs[tg][ci];
                ull hv = *(const ull*)&w1s[ci][h2];
                acc = fma2(pk2(wv, wv), hv, acc);
            }
        }
        float g0, g1;
        upk2(g0, g1, acc);
        g_GH[(tau0 + tg) * HID + h0 + h2]     = g0;
        g_GH[(tau0 + tg) * HID + h0 + h2 + 1] = g1;
    }

    // ---- Econst[h] = b1[h] + sum_c beff[c]*W1[c,h] (blocks 0..15) ----
    if (b < 16) {
        __syncthreads();
        int h0e = b * 32, hl = t & 31, seg = t >> 5;
        float part = (seg == 0) ? b1[h0e + hl] : 0.f;
        #pragma unroll 8
        for (int c = seg * 32; c < seg * 32 + 32; c++)
            part += g_bB[c] * w1[(size_t)c * HID + h0e + hl];
        ecs[seg][hl] = part;
        __syncthreads();
        if (t < 32) {
            float s = 0.f;
            #pragma unroll
            for (int q = 0; q < 8; q++) s += ecs[q][t];
            g_Ec[h0e + t] = s;
        }
    }
}

// ---------------------------------------------------------------------------
// E[b,i,h] = Econst[h] + sum_{tau} GH[tau,h] * xs[255+i-tau]  (unchanged R3)
// ---------------------------------------------------------------------------
__global__ void __launch_bounds__(256)
k_E(const float* __restrict__ x) {
    __shared__ float xs[288];
    __shared__ float GHs[32][132];
    int b = blockIdx.x, ht = blockIdx.y, t = threadIdx.x;
    int h0 = ht * 128;
    xs[t] = x[b * TTOT + 256 + t];
    if (t < 32) xs[256 + t] = 0.f;
    int h_l = t & 127, ig = t >> 7;
    float acc[16];
    #pragma unroll
    for (int r = 0; r < 16; r++) acc[r] = 0.f;

    for (int tc = 0; tc < LAGS; tc += 32) {
        __syncthreads();
        #pragma unroll
        for (int e = 0; e < 16; e++) {
            int idx = e * 256 + t;
            int row = idx >> 7, col = idx & 127;
            GHs[row][col] = g_GH[(tc + row) * HID + h0 + col];
        }
        __syncthreads();
        float xw[47];
        int base = 255 + ig * 16 - tc - 31;
        #pragma unroll
        for (int q = 0; q < 47; q++) xw[q] = xs[base + q];
        #pragma unroll
        for (int tt = 0; tt < 32; tt++) {
            float wv = GHs[tt][h_l];
            #pragma unroll
            for (int r = 0; r < 16; r++)
                acc[r] += wv * xw[r + 31 - tt];
        }
    }
    float ec = g_Ec[h0 + h_l];
    #pragma unroll
    for (int r = 0; r < 16; r++)
        g_E[(size_t)(b * DEC + ig * 16 + r) * HID + h0 + h_l] = acc[r] + ec;
}

// ---------------------------------------------------------------------------
// Decode: 1 batch/block, E register-resident, eager updates (unchanged R3).
// ---------------------------------------------------------------------------
__global__ void __launch_bounds__(256, 1)
k_decode(const float* __restrict__ w2, const float* __restrict__ b2,
         float* __restrict__ out) {
    extern __shared__ float sm[];
    float* Gs  = sm;
    float* red = sm + 31 * HID;
    int t = threadIdx.x, b = blockIdx.x;
    int wid = t >> 5, lane = t & 31;
    for (int e = t; e < 31 * HID; e += 256) Gs[e] = g_GH[e];
    float2 a[DEC];
    const float2* Ef = (const float2*)(g_E + (size_t)b * DEC * HID);
    #pragma unroll
    for (int i = 0; i < DEC; i++) a[i] = Ef[i * 256 + t];
    float2 w2v = ((const float2*)w2)[t];
    float b2v = b2[0];
    __syncthreads();
    const float2* G2 = (const float2*)Gs;
    #pragma unroll
    for (int i = 0; i < DEC; i++) {
        float p = fmaxf(a[i].x, 0.f) * w2v.x + fmaxf(a[i].y, 0.f) * w2v.y;
        #pragma unroll
        for (int off = 16; off > 0; off >>= 1)
            p += __shfl_down_sync(0xffffffffu, p, off);
        if (lane == 0) red[(i & 1) * 8 + wid] = p;
        __syncthreads();
        float o = b2v;
        #pragma unroll
        for (int q = 0; q < 8; q++) o += red[(i & 1) * 8 + q];
        if (t == 0) out[b * DEC + i] = o;
        #pragma unroll
        for (int ii = i + 1; ii < DEC; ii++) {
            float2 g = G2[(ii - 1 - i) * 256 + t];
            a[ii].x += g.x * o;
            a[ii].y += g.y * o;
        }
    }
}

// ---------------------------------------------------------------------------
extern "C" void kernel_launch(void* const* d_in, const int* in_sizes, int n_in,
                              void* d_out, int out_size) {
    const float* x   = (const float*)d_in[0];
    const float* c0w = (const float*)d_in[1];
    const float* c0b = (const float*)d_in[2];
    const float* cw  = (const float*)d_in[3];
    const float* cb  = (const float*)d_in[4];
    const float* w1  = (const float*)d_in[5];
    const float* b1  = (const float*)d_in[6];
    const float* w2  = (const float*)d_in[7];
    const float* b2  = (const float*)d_in[8];
    float* out = (float*)d_out;

    k_compose_all<<<NBC, 256>>>(c0w, c0b, cw, cb, w1, b1);
    k_E<<<dim3(64, 4), 256>>>(x);

    const int dec_smem = (31 * HID + 16) * (int)sizeof(float);
    cudaFuncSetAttribute(k_decode, cudaFuncAttributeMaxDynamicSharedMemorySize,
                         dec_smem);
    k_decode<<<BATCH, 256, dec_smem>>>(w2, b2, out);
}

// round 5
// speedup vs baseline: 3.9814x; 1.8052x over previous
#include <cuda_runtime.h>

#define CC    256
#define LAGS  256
#define BATCH 64
#define DEC   32
#define TTOT  543
#define HID   512
#define NBC   256
#define NGRP  16

typedef unsigned long long ull;

// Persistent scratch (no allocations allowed).
__device__ float g_PA[4 * LAGS * CC];
__device__ float g_PB[4 * LAGS * CC];
__device__ float g_bA[CC];
__device__ float g_bB[CC];
__device__ float g_GH[LAGS * HID];   // GH[tau][h] = sum_c Weff[c,tau]*W1[c,h]
__device__ float g_Ec[HID];          // b1 + beff^T W1
__device__ float g_E[BATCH * DEC * HID];
__device__ unsigned g_cnt[NGRP * 32];
__device__ unsigned g_root;
__device__ volatile unsigned g_gen;

__device__ __forceinline__ ull pk2(float x, float y) {
    ull r;
    asm("mov.b64 %0, {%1, %2};" : "=l"(r) : "f"(x), "f"(y));
    return r;
}
__device__ __forceinline__ void upk2(float& x, float& y, ull v) {
    asm("mov.b64 {%0, %1}, %2;" : "=f"(x), "=f"(y) : "l"(v));
}
__device__ __forceinline__ ull fma2(ull a, ull b, ull c) {
    ull d;
    asm("fma.rn.f32x2 %0, %1, %2, %3;" : "=l"(d) : "l"(a), "l"(b), "l"(c));
    return d;
}

__device__ __forceinline__ void gridbar(int b) {
    __syncthreads();
    if (threadIdx.x == 0) {
        unsigned gen = g_gen;
        __threadfence();
        bool last = false;
        if (atomicAdd(&g_cnt[(b >> 4) * 32], 1u) == 15u) {
            if (atomicAdd(&g_root, 1u) == NGRP - 1) last = true;
        }
        if (last) {
            #pragma unroll
            for (int q = 0; q < NGRP; q++) g_cnt[q * 32] = 0u;
            g_root = 0u;
            __threadfence();
            g_gen = gen + 1;
        } else {
            while (g_gen == gen) { }
            __threadfence();
        }
    }
    __syncthreads();
}

// ---------------------------------------------------------------------------
// Persistent compose: init + 7 layers + GH + Econst.
// Bias chain now warp-parallel (blocks 224..255, one warp per channel).
// ---------------------------------------------------------------------------
__global__ void __launch_bounds__(256, 2)
k_compose_all(const float* __restrict__ c0w, const float* __restrict__ c0b,
              const float* __restrict__ cw,  const float* __restrict__ cb,
              const float* __restrict__ w1,  const float* __restrict__ b1) {
    __shared__ float As[16][17], Ss[16][17];
    __shared__ float B0s[16][68], B1s[16][68];
    __shared__ float Wgs[16][33], w1s[32][34], ecs[8][33];
    int b = blockIdx.x, t = threadIdx.x;

    // ---- init: zero partial buffers; conv0 taps into PA slot 0 ----
    {
        int base = b * 2048;
        #pragma unroll
        for (int e = 0; e < 8; e++) {
            int idx = base + e * 256 + t;
            if (idx < 4 * LAGS * CC) g_PA[idx] = 0.f;
            else                     g_PB[idx - 4 * LAGS * CC] = 0.f;
        }
        __syncthreads();
        if (b == 0) {
            g_PA[t]      = c0w[t * 2 + 1];   // tau 0
            g_PA[CC + t] = c0w[t * 2 + 0];   // tau 1
            g_bA[t]      = c0b[t];
        }
    }
    gridbar(b);

    // ---- 7 layers ----
    int d = 2;
    for (int j = 0; j < 7; j++) {
        const float* Ps   = (j & 1) ? g_PB : g_PA;
        float*       Pd   = (j & 1) ? g_PA : g_PB;
        const float* srcb = (j & 1) ? g_bB : g_bA;
        float*       dstb = (j & 1) ? g_bA : g_bB;
        const float* w = cw + (size_t)j * CC * CC * 2;
        int R  = 4 << j;
        int TT = (R + 15) >> 4;          // 1,1,1,2,4,8,16
        int nuse = TT * 16;
        if (b < nuse) {
            int kp = b & 3, cot = (b >> 2) & 3, taut = b >> 4;
            int tau0 = taut * 16, co0 = cot * 64, k0 = kp * 64;
            int tl  = t & 15;            // tau within tile
            int col = (t >> 4) * 4;      // co within tile (4 each)
            ull acc0 = 0ull, acc1 = 0ull;
            const float2* wp2 = (const float2*)w;
            for (int kc = 0; kc < 64; kc += 16) {
                __syncthreads();
                {
                    int kk = t & 15, r = t >> 4;
                    int ci = k0 + kc + kk;
                    int ra = (tau0 + r) * CC + ci;
                    As[kk][r] = Ps[ra] + Ps[65536 + ra] + Ps[131072 + ra]
                              + Ps[196608 + ra];
                    int ts = tau0 + r - d;
                    float vs = 0.f;
                    if (ts >= 0) {
                        int rs = ts * CC + ci;
                        vs = Ps[rs] + Ps[65536 + rs] + Ps[131072 + rs]
                           + Ps[196608 + rs];
                    }
                    Ss[kk][r] = vs;
                    int ci_l = t & 15, cw_l = t >> 4;
                    #pragma unroll
                    for (int p = 0; p < 4; p++) {
                        int co = p * 16 + cw_l;
                        float2 wv = wp2[(size_t)(co0 + co) * CC + k0 + kc + ci_l];
                        B0s[ci_l][co] = wv.x;
                        B1s[ci_l][co] = wv.y;
                    }
                }
                __syncthreads();
                #pragma unroll
                for (int kk = 0; kk < 16; kk++) {
                    float a = As[kk][tl], s = Ss[kk][tl];
                    ull a2 = pk2(a, a), s2 = pk2(s, s);
                    ull p0 = *(const ull*)&B1s[kk][col];
                    ull p1 = *(const ull*)&B1s[kk][col + 2];
                    ull q0 = *(const ull*)&B0s[kk][col];
                    ull q1 = *(const ull*)&B0s[kk][col + 2];
                    acc0 = fma2(a2, p0, acc0);
                    acc0 = fma2(s2, q0, acc0);
                    acc1 = fma2(a2, p1, acc1);
                    acc1 = fma2(s2, q1, acc1);
                }
            }
            float c0, c1, c2, c3;
            upk2(c0, c1, acc0);
            upk2(c2, c3, acc1);
            float4 v = make_float4(c0, c1, c2, c3);
            *(float4*)&Pd[kp * 65536 + (tau0 + tl) * CC + co0 + col] = v;
        }
        // bias chain: blocks 224..255, one warp per output channel, lanes
        // split the 256-term dot product (all loads independent -> 1 latency).
        if (b >= 224) {
            int wid = t >> 5, lane = t & 31;
            int co = (b - 224) * 8 + wid;
            const float2* wp2b = (const float2*)w;
            float acc = 0.f;
            #pragma unroll
            for (int q = 0; q < 8; q++) {
                int ci = q * 32 + lane;
                float2 wv = wp2b[(size_t)co * CC + ci];
                acc += (wv.x + wv.y) * srcb[ci];
            }
            #pragma unroll
            for (int off = 16; off > 0; off >>= 1)
                acc += __shfl_down_sync(0xffffffffu, acc, off);
            if (lane == 0) dstb[co] = acc + cb[(size_t)j * CC + co];
        }
        gridbar(b);
        d <<= 1;
    }

    // ---- GH[tau0..+15][h0..+31] from final partials (in g_PB) ----
    {
        int tau0 = (b >> 4) * 16, h0 = (b & 15) * 32;
        int tg = t >> 4, h2 = (t & 15) * 2;
        ull acc = 0ull;
        for (int cc2 = 0; cc2 < CC; cc2 += 32) {
            __syncthreads();
            #pragma unroll
            for (int e = 0; e < 2; e++) {
                int idx = e * 256 + t;
                int tr = idx >> 5, cl = idx & 31;
                int ra = (tau0 + tr) * CC + cc2 + cl;
                Wgs[tr][cl] = g_PB[ra] + g_PB[65536 + ra] + g_PB[131072 + ra]
                            + g_PB[196608 + ra];
            }
            #pragma unroll
            for (int e = 0; e < 4; e++) {
                int idx = e * 256 + t;
                int cr = idx >> 5, hl = idx & 31;
                w1s[cr][hl] = w1[(size_t)(cc2 + cr) * HID + h0 + hl];
            }
            __syncthreads();
            #pragma unroll
            for (int ci = 0; ci < 32; ci++) {
                float wv = Wgs[tg][ci];
                ull hv = *(const ull*)&w1s[ci][h2];
                acc = fma2(pk2(wv, wv), hv, acc);
            }
        }
        float g0, g1;
        upk2(g0, g1, acc);
        g_GH[(tau0 + tg) * HID + h0 + h2]     = g0;
        g_GH[(tau0 + tg) * HID + h0 + h2 + 1] = g1;
    }

    // ---- Econst[h] = b1[h] + sum_c beff[c]*W1[c,h] (blocks 0..15) ----
    if (b < 16) {
        __syncthreads();
        int h0e = b * 32, hl = t & 31, seg = t >> 5;
        float part = (seg == 0) ? b1[h0e + hl] : 0.f;
        #pragma unroll 8
        for (int c = seg * 32; c < seg * 32 + 32; c++)
            part += g_bB[c] * w1[(size_t)c * HID + h0e + hl];
        ecs[seg][hl] = part;
        __syncthreads();
        if (t < 32) {
            float s = 0.f;
            #pragma unroll
            for (int q = 0; q < 8; q++) s += ecs[q][t];
            g_Ec[h0e + t] = s;
        }
    }
}

// ---------------------------------------------------------------------------
// E[b,i,h] = Econst[h] + sum_{tau} GH[tau,h] * xs[255+i-tau]  (unchanged)
// ---------------------------------------------------------------------------
__global__ void __launch_bounds__(256)
k_E(const float* __restrict__ x) {
    __shared__ float xs[288];
    __shared__ float GHs[32][132];
    int b = blockIdx.x, ht = blockIdx.y, t = threadIdx.x;
    int h0 = ht * 128;
    xs[t] = x[b * TTOT + 256 + t];
    if (t < 32) xs[256 + t] = 0.f;
    int h_l = t & 127, ig = t >> 7;
    float acc[16];
    #pragma unroll
    for (int r = 0; r < 16; r++) acc[r] = 0.f;

    for (int tc = 0; tc < LAGS; tc += 32) {
        __syncthreads();
        #pragma unroll
        for (int e = 0; e < 16; e++) {
            int idx = e * 256 + t;
            int row = idx >> 7, col = idx & 127;
            GHs[row][col] = g_GH[(tc + row) * HID + h0 + col];
        }
        __syncthreads();
        float xw[47];
        int base = 255 + ig * 16 - tc - 31;
        #pragma unroll
        for (int q = 0; q < 47; q++) xw[q] = xs[base + q];
        #pragma unroll
        for (int tt = 0; tt < 32; tt++) {
            float wv = GHs[tt][h_l];
            #pragma unroll
            for (int r = 0; r < 16; r++)
                acc[r] += wv * xw[r + 31 - tt];
        }
    }
    float ec = g_Ec[h0 + h_l];
    #pragma unroll
    for (int r = 0; r < 16; r++)
        g_E[(size_t)(b * DEC + ig * 16 + r) * HID + h0 + h_l] = acc[r] + ec;
}

// ---------------------------------------------------------------------------
// Decode: 1 batch/block, E register-resident, eager updates (unchanged).
// ---------------------------------------------------------------------------
__global__ void __launch_bounds__(256, 1)
k_decode(const float* __restrict__ w2, const float* __restrict__ b2,
         float* __restrict__ out) {
    extern __shared__ float sm[];
    float* Gs  = sm;
    float* red = sm + 31 * HID;
    int t = threadIdx.x, b = blockIdx.x;
    int wid = t >> 5, lane = t & 31;
    for (int e = t; e < 31 * HID; e += 256) Gs[e] = g_GH[e];
    float2 a[DEC];
    const float2* Ef = (const float2*)(g_E + (size_t)b * DEC * HID);
    #pragma unroll
    for (int i = 0; i < DEC; i++) a[i] = Ef[i * 256 + t];
    float2 w2v = ((const float2*)w2)[t];
    float b2v = b2[0];
    __syncthreads();
    const float2* G2 = (const float2*)Gs;
    #pragma unroll
    for (int i = 0; i < DEC; i++) {
        float p = fmaxf(a[i].x, 0.f) * w2v.x + fmaxf(a[i].y, 0.f) * w2v.y;
        #pragma unroll
        for (int off = 16; off > 0; off >>= 1)
            p += __shfl_down_sync(0xffffffffu, p, off);
        if (lane == 0) red[(i & 1) * 8 + wid] = p;
        __syncthreads();
        float o = b2v;
        #pragma unroll
        for (int q = 0; q < 8; q++) o += red[(i & 1) * 8 + q];
        if (t == 0) out[b * DEC + i] = o;
        #pragma unroll
        for (int ii = i + 1; ii < DEC; ii++) {
            float2 g = G2[(ii - 1 - i) * 256 + t];
            a[ii].x += g.x * o;
            a[ii].y += g.y * o;
        }
    }
}

// ---------------------------------------------------------------------------
extern "C" void kernel_launch(void* const* d_in, const int* in_sizes, int n_in,
                              void* d_out, int out_size) {
    const float* x   = (const float*)d_in[0];
    const float* c0w = (const float*)d_in[1];
    const float* c0b = (const float*)d_in[2];
    const float* cw  = (const float*)d_in[3];
    const float* cb  = (const float*)d_in[4];
    const float* w1  = (const float*)d_in[5];
    const float* b1  = (const float*)d_in[6];
    const float* w2  = (const float*)d_in[7];
    const float* b2  = (const float*)d_in[8];
    float* out = (float*)d_out;

    k_compose_all<<<NBC, 256>>>(c0w, c0b, cw, cb, w1, b1);
    k_E<<<dim3(64, 4), 256>>>(x);

    const int dec_smem = (31 * HID + 16) * (int)sizeof(float);
    cudaFuncSetAttribute(k_decode, cudaFuncAttributeMaxDynamicSharedMemorySize,
                         dec_smem);
    k_decode<<<BATCH, 256, dec_smem>>>(w2, b2, out);
}